// round 12
// baseline (speedup 1.0000x reference)
#include <cuda_runtime.h>
#include <math.h>

#define N_NODES 100000
#define N_EDGES 1250000
#define D 64
#define EPSF 1e-8f
#define NEG_INF __int_as_float(0xff800000)

typedef unsigned long long u64;

// ---------------- scratch (static device memory; no allocation) ----------------
__device__ float g_A[N_NODES * D];      // h @ W1[:, :64].T
__device__ float g_B[N_NODES * D];      // h @ W1[:, 64:].T
__device__ float g_sumA[N_NODES * D];   // seg_sum over dst of A[src]
__device__ float g_maxA[N_NODES * D];   // seg_max over dst of A[src]
__device__ float g_sumwA[N_NODES * D];  // seg_sum over dst of eig*A[src] (raw)
__device__ float g_h2[N_NODES * D];     // posttrans output (pre-BN)
__device__ float g_absum[N_NODES];      // seg_sum |eig|
__device__ float g_sEig[N_NODES];       // seg_sum eig
__device__ float g_deg[N_NODES];        // degree (float)
__device__ float g_stats[2 * D];        // per-feature sum, sumsq of h2
__device__ float g_scale[D];            // BN scale
__device__ float g_shift[D];            // BN shift
__device__ float g_W2T[256 * D];        // W2 transposed: [k][o]
// CSR machinery
__device__ int g_degi[N_NODES];         // int degree
__device__ int g_start[N_NODES];        // CSR row start (exclusive scan)
__device__ int g_cursor[N_NODES];       // scatter cursors
__device__ int2 g_epack[N_EDGES];       // (src, eig bits) grouped by dst
__device__ int g_bsum[128];             // scan block sums

// ---------------- f32x2 helpers ----------------
#define FMA2(d, a, b, c) \
    asm("fma.rn.f32x2 %0, %1, %2, %3;" : "=l"(d) : "l"(a), "l"(b), "l"(c))
__device__ __forceinline__ float2 unpack2(u64 v) {
    float2 r;
    asm("mov.b64 {%0,%1}, %2;" : "=f"(r.x), "=f"(r.y) : "l"(v));
    return r;
}

// ---------------- K0: prep (zero degi/stats + transpose W2) ----------------
__global__ __launch_bounds__(256) void k_prep(const float* __restrict__ W2) {
    int i = blockIdx.x * 256 + threadIdx.x;
    if (i < N_NODES) g_degi[i] = 0;
    if (i < 2 * D) g_stats[i] = 0.0f;
    if (i < D * 256) {            // i = o*256 + k
        int o = i >> 8, k = i & 255;
        g_W2T[k * D + o] = W2[i];
    }
}

// ---------------- K1: node pretrans  A,B = h @ [W1a|W1b].T (f32x2) ----------------
// 256 threads, 128 nodes/block. Thread tile: 8 nodes (4 pairs) x 8 outputs.
#define HT_S 130     // sHt row stride (even -> 8B-aligned pairs; 2-way STS conflict)
#define WD1_S 260    // sWtD row stride (mult of 4 -> 16B-aligned)
__global__ __launch_bounds__(256) void k_pretrans(const float* __restrict__ h,
                                                  const float* __restrict__ W1) {
    extern __shared__ float dsm1[];
    float* sWtD = dsm1;                  // [k][2*o] duplicated weights, 64 x 260
    float* sHt  = dsm1 + 64 * WD1_S;     // [k][nl], 64 x 130
    int t = threadIdx.x;
    int base = blockIdx.x * 128;

    for (int idx = t; idx < 64 * 128; idx += 256) {
        int o = idx >> 7, kk = idx & 127;    // W1 row-major [o][kk]
        float v = W1[idx];
        int k = (kk < D) ? kk : kk - D;
        int c = (kk < D) ? o : o + D;        // combined output index [A|B]
        *reinterpret_cast<float2*>(&sWtD[k * WD1_S + 2 * c]) = make_float2(v, v);
    }
    for (int idx = t; idx < 128 * 64; idx += 256) {
        int nl = idx >> 6, k = idx & 63;
        int n = base + nl;
        sHt[k * HT_S + nl] = (n < N_NODES) ? h[n * D + k] : 0.0f;
    }
    __syncthreads();

    int tx = t & 15, ty = t >> 4;   // tx: 8 outputs; ty: 8 nodes (4 pairs)
    u64 acc[4][8];
#pragma unroll
    for (int p = 0; p < 4; p++)
#pragma unroll
        for (int j = 0; j < 8; j++) acc[p][j] = 0ULL;

#pragma unroll 2
    for (int k = 0; k < 64; k++) {
        const float* hrow = &sHt[k * HT_S + ty * 8];
        u64 a0 = *reinterpret_cast<const u64*>(hrow);
        u64 a1 = *reinterpret_cast<const u64*>(hrow + 2);
        u64 a2 = *reinterpret_cast<const u64*>(hrow + 4);
        u64 a3 = *reinterpret_cast<const u64*>(hrow + 6);
        const float* wrow = &sWtD[k * WD1_S + tx * 16];
        ulonglong2 b01 = *reinterpret_cast<const ulonglong2*>(wrow);
        ulonglong2 b23 = *reinterpret_cast<const ulonglong2*>(wrow + 4);
        ulonglong2 b45 = *reinterpret_cast<const ulonglong2*>(wrow + 8);
        ulonglong2 b67 = *reinterpret_cast<const ulonglong2*>(wrow + 12);
#define PT_STEP(p, av) \
        FMA2(acc[p][0], av, b01.x, acc[p][0]); FMA2(acc[p][1], av, b01.y, acc[p][1]); \
        FMA2(acc[p][2], av, b23.x, acc[p][2]); FMA2(acc[p][3], av, b23.y, acc[p][3]); \
        FMA2(acc[p][4], av, b45.x, acc[p][4]); FMA2(acc[p][5], av, b45.y, acc[p][5]); \
        FMA2(acc[p][6], av, b67.x, acc[p][6]); FMA2(acc[p][7], av, b67.y, acc[p][7]);
        PT_STEP(0, a0); PT_STEP(1, a1); PT_STEP(2, a2); PT_STEP(3, a3);
#undef PT_STEP
    }

#pragma unroll
    for (int p = 0; p < 4; p++) {
        float2 u0 = unpack2(acc[p][0]), u1 = unpack2(acc[p][1]);
        float2 u2 = unpack2(acc[p][2]), u3 = unpack2(acc[p][3]);
        float2 u4 = unpack2(acc[p][4]), u5 = unpack2(acc[p][5]);
        float2 u6 = unpack2(acc[p][6]), u7 = unpack2(acc[p][7]);
#pragma unroll
        for (int half = 0; half < 2; half++) {
            int n = base + ty * 8 + 2 * p + half;
            if (n >= N_NODES) continue;
            float4 v0, v1;
            if (half == 0) {
                v0 = make_float4(u0.x, u1.x, u2.x, u3.x);
                v1 = make_float4(u4.x, u5.x, u6.x, u7.x);
            } else {
                v0 = make_float4(u0.y, u1.y, u2.y, u3.y);
                v1 = make_float4(u4.y, u5.y, u6.y, u7.y);
            }
            if (tx < 8) {
                *reinterpret_cast<float4*>(&g_A[n * D + tx * 8])     = v0;
                *reinterpret_cast<float4*>(&g_A[n * D + tx * 8 + 4]) = v1;
            } else {
                int o = tx * 8 - D;
                *reinterpret_cast<float4*>(&g_B[n * D + o])     = v0;
                *reinterpret_cast<float4*>(&g_B[n * D + o + 4]) = v1;
            }
        }
    }
}

// ---------------- CSR build ----------------
__global__ __launch_bounds__(256) void k_deg(const int* __restrict__ dst) {
    int e = blockIdx.x * 256 + threadIdx.x;
    if (e < N_EDGES) atomicAdd(&g_degi[__ldg(&dst[e])], 1);
}

__global__ __launch_bounds__(1024) void k_scan1() {
    __shared__ int wsum[32];
    int t = threadIdx.x;
    int lane = t & 31, wid = t >> 5;
    int n = blockIdx.x * 1024 + t;
    int v = (n < N_NODES) ? g_degi[n] : 0;
    int inc = v;
#pragma unroll
    for (int off = 1; off < 32; off <<= 1) {
        int y = __shfl_up_sync(0xffffffffu, inc, off);
        if (lane >= off) inc += y;
    }
    if (lane == 31) wsum[wid] = inc;
    __syncthreads();
    if (wid == 0) {
        int s = wsum[lane];
        int inc2 = s;
#pragma unroll
        for (int off = 1; off < 32; off <<= 1) {
            int y = __shfl_up_sync(0xffffffffu, inc2, off);
            if (lane >= off) inc2 += y;
        }
        wsum[lane] = inc2 - s;            // exclusive warp offset
        if (lane == 31) g_bsum[blockIdx.x] = inc2;   // block total
    }
    __syncthreads();
    if (n < N_NODES) g_start[n] = inc - v + wsum[wid];
}

__global__ __launch_bounds__(128) void k_scan2(int nblk) {
    __shared__ int s[128];
    int t = threadIdx.x;
    int v = (t < nblk) ? g_bsum[t] : 0;
    s[t] = v;
    __syncthreads();
#pragma unroll
    for (int off = 1; off < 128; off <<= 1) {
        int x = (t >= off) ? s[t - off] : 0;
        __syncthreads();
        s[t] += x;
        __syncthreads();
    }
    if (t < nblk) g_bsum[t] = s[t] - v;   // exclusive
}

__global__ __launch_bounds__(256) void k_scan3() {
    int n = blockIdx.x * 256 + threadIdx.x;
    if (n < N_NODES) {
        int st = g_start[n] + g_bsum[n >> 10];
        g_start[n] = st;
        g_cursor[n] = st;
    }
}

__global__ __launch_bounds__(256) void k_scatter(const int* __restrict__ src,
                                                 const int* __restrict__ dst,
                                                 const float* __restrict__ eig) {
    int e = blockIdx.x * 256 + threadIdx.x;
    if (e < N_EDGES) {
        int d = __ldg(&dst[e]);
        int pos = atomicAdd(&g_cursor[d], 1);
        g_epack[pos] = make_int2(__ldg(&src[e]), __float_as_int(__ldg(&eig[e])));
    }
}

// ---------------- K2: CSR gather (one warp per node, unroll-2 pipeline) ----------------
__global__ __launch_bounds__(256) void k_gather() {
    int t = threadIdx.x;
    int n = blockIdx.x * 8 + (t >> 5);     // grid*8 == N_NODES exactly
    int lane = t & 31;
    int grp = lane >> 4;                   // 0/1
    int c = lane & 15;                     // feature quad

    int st = g_start[n];
    int deg = g_degi[n];
    int en = st + deg;

    float4 sum = make_float4(0.f, 0.f, 0.f, 0.f);
    float4 sw  = make_float4(0.f, 0.f, 0.f, 0.f);
    float4 mx  = make_float4(NEG_INF, NEG_INF, NEG_INF, NEG_INF);
    float ab = 0.f, sE = 0.f;

    int i = st + grp;
    for (; i + 2 < en; i += 4) {           // 2 edges in flight per group
        int2 pa = __ldg(&g_epack[i]);
        int2 pb = __ldg(&g_epack[i + 2]);
        float4 aa = *reinterpret_cast<const float4*>(&g_A[pa.x * D + c * 4]);
        float4 abv = *reinterpret_cast<const float4*>(&g_A[pb.x * D + c * 4]);
        float wa = __int_as_float(pa.y), wb = __int_as_float(pb.y);
        sum.x += aa.x + abv.x; sum.y += aa.y + abv.y;
        sum.z += aa.z + abv.z; sum.w += aa.w + abv.w;
        mx.x = fmaxf(mx.x, fmaxf(aa.x, abv.x)); mx.y = fmaxf(mx.y, fmaxf(aa.y, abv.y));
        mx.z = fmaxf(mx.z, fmaxf(aa.z, abv.z)); mx.w = fmaxf(mx.w, fmaxf(aa.w, abv.w));
        sw.x += wa * aa.x + wb * abv.x; sw.y += wa * aa.y + wb * abv.y;
        sw.z += wa * aa.z + wb * abv.z; sw.w += wa * aa.w + wb * abv.w;
        ab += fabsf(wa) + fabsf(wb); sE += wa + wb;
    }
    if (i < en) {
        int2 p = __ldg(&g_epack[i]);
        float w = __int_as_float(p.y);
        float4 a = *reinterpret_cast<const float4*>(&g_A[p.x * D + c * 4]);
        sum.x += a.x; sum.y += a.y; sum.z += a.z; sum.w += a.w;
        mx.x = fmaxf(mx.x, a.x); mx.y = fmaxf(mx.y, a.y);
        mx.z = fmaxf(mx.z, a.z); mx.w = fmaxf(mx.w, a.w);
        sw.x += w * a.x; sw.y += w * a.y; sw.z += w * a.z; sw.w += w * a.w;
        ab += fabsf(w); sE += w;
    }

    sum.x += __shfl_down_sync(0xffffffffu, sum.x, 16);
    sum.y += __shfl_down_sync(0xffffffffu, sum.y, 16);
    sum.z += __shfl_down_sync(0xffffffffu, sum.z, 16);
    sum.w += __shfl_down_sync(0xffffffffu, sum.w, 16);
    mx.x = fmaxf(mx.x, __shfl_down_sync(0xffffffffu, mx.x, 16));
    mx.y = fmaxf(mx.y, __shfl_down_sync(0xffffffffu, mx.y, 16));
    mx.z = fmaxf(mx.z, __shfl_down_sync(0xffffffffu, mx.z, 16));
    mx.w = fmaxf(mx.w, __shfl_down_sync(0xffffffffu, mx.w, 16));
    sw.x += __shfl_down_sync(0xffffffffu, sw.x, 16);
    sw.y += __shfl_down_sync(0xffffffffu, sw.y, 16);
    sw.z += __shfl_down_sync(0xffffffffu, sw.z, 16);
    sw.w += __shfl_down_sync(0xffffffffu, sw.w, 16);
    ab += __shfl_down_sync(0xffffffffu, ab, 16);
    sE += __shfl_down_sync(0xffffffffu, sE, 16);

    if (grp == 0) {
        int o = n * D + c * 4;
        *reinterpret_cast<float4*>(&g_sumA[o])  = sum;
        *reinterpret_cast<float4*>(&g_maxA[o])  = mx;
        *reinterpret_cast<float4*>(&g_sumwA[o]) = sw;
        if (c == 0) {
            g_deg[n] = (float)deg;
            g_absum[n] = ab;
            g_sEig[n] = sE;
        }
    }
}

// ---------------- K4: node posttrans GEMM + BN partial stats (f32x2) ----------------
// 256 threads, 128 nodes/block. hc built chunk-by-chunk, stored K-major.
#define HC2_S 130   // sHC row stride [k][node]
#define WD2_S 132   // sW2D row stride [k][2*o]
__global__ __launch_bounds__(256) void k_post(const float* __restrict__ h,
                                              const float* __restrict__ snorm,
                                              const float* __restrict__ b1,
                                              const float* __restrict__ b2) {
    extern __shared__ float dsm2[];
    float* sHC  = dsm2;                    // 64 x 130
    float* sW2D = dsm2 + 64 * HC2_S;       // 64 x 132 duplicated
    __shared__ float sStats[2 * D];
    __shared__ float sDeg[128], sAb[128], sSE[128];

    int t = threadIdx.x;
    int base = blockIdx.x * 128;

    if (t < 128) {
        int n = base + t;
        float deg = 0.0f, ab = EPSF, sE = 0.0f;
        if (n < N_NODES) { deg = g_deg[n]; ab = g_absum[n] + EPSF; sE = g_sEig[n]; }
        sDeg[t] = deg; sAb[t] = ab; sSE[t] = sE;
        sStats[t] = 0.0f;
    }

    int f = t & 63;
    int quarter = t >> 6;          // 0..3
    float b1f = __ldg(&b1[f]);

    int tx = t & 7, ty = t >> 3;   // tx: 8 outputs; ty: 0..31, 4 nodes (2 pairs)
    u64 acc[2][8];
#pragma unroll
    for (int p = 0; p < 2; p++)
#pragma unroll
        for (int j = 0; j < 8; j++) acc[p][j] = 0ULL;

#pragma unroll
    for (int cch = 0; cch < 4; cch++) {
        __syncthreads();
        for (int i = t; i < 4096; i += 256) {
            float v = g_W2T[cch * 4096 + i];
            int kl = i >> 6, o = i & 63;
            *reinterpret_cast<float2*>(&sW2D[kl * WD2_S + 2 * o]) = make_float2(v, v);
        }
        for (int r = 0; r < 32; r++) {
            int nl = quarter + r * 4;
            int n = base + nl;
            float v = 0.0f;
            if (n < N_NODES) {
                int o = n * D + f;
                if (cch == 0) {
                    v = h[o];
                } else if (cch == 1) {
                    float deg = sDeg[nl];
                    v = (g_sumA[o] + deg * (g_B[o] + b1f)) / fmaxf(deg, 1.0f);
                } else if (cch == 2) {
                    v = (sDeg[nl] > 0.0f) ? (g_maxA[o] + g_B[o] + b1f) : 0.0f;
                } else {
                    float sE = sSE[nl], ab = sAb[nl];
                    v = fabsf((g_sumwA[o] + sE * (g_B[o] + b1f)) / ab - (sE / ab) * h[o]);
                }
            }
            sHC[f * HC2_S + nl] = v;     // K-major
        }
        __syncthreads();
#pragma unroll 4
        for (int k = 0; k < 64; k++) {
            const float* arow = &sHC[k * HC2_S + ty * 4];
            u64 a0 = *reinterpret_cast<const u64*>(arow);
            u64 a1 = *reinterpret_cast<const u64*>(arow + 2);
            const float* wrow = &sW2D[k * WD2_S + tx * 16];
            ulonglong2 b01 = *reinterpret_cast<const ulonglong2*>(wrow);
            ulonglong2 b23 = *reinterpret_cast<const ulonglong2*>(wrow + 4);
            ulonglong2 b45 = *reinterpret_cast<const ulonglong2*>(wrow + 8);
            ulonglong2 b67 = *reinterpret_cast<const ulonglong2*>(wrow + 12);
#define PP_STEP(p, av) \
            FMA2(acc[p][0], av, b01.x, acc[p][0]); FMA2(acc[p][1], av, b01.y, acc[p][1]); \
            FMA2(acc[p][2], av, b23.x, acc[p][2]); FMA2(acc[p][3], av, b23.y, acc[p][3]); \
            FMA2(acc[p][4], av, b45.x, acc[p][4]); FMA2(acc[p][5], av, b45.y, acc[p][5]); \
            FMA2(acc[p][6], av, b67.x, acc[p][6]); FMA2(acc[p][7], av, b67.y, acc[p][7]);
            PP_STEP(0, a0); PP_STEP(1, a1);
#undef PP_STEP
        }
    }

    float4 bA = *reinterpret_cast<const float4*>(&b2[tx * 8]);
    float4 bB = *reinterpret_cast<const float4*>(&b2[tx * 8 + 4]);
    float s0 = 0, s1 = 0, s2 = 0, s3 = 0, s4 = 0, s5 = 0, s6 = 0, s7 = 0;
    float q0 = 0, q1 = 0, q2 = 0, q3 = 0, q4 = 0, q5 = 0, q6 = 0, q7 = 0;
#pragma unroll
    for (int p = 0; p < 2; p++) {
        float2 u0 = unpack2(acc[p][0]), u1 = unpack2(acc[p][1]);
        float2 u2 = unpack2(acc[p][2]), u3 = unpack2(acc[p][3]);
        float2 u4 = unpack2(acc[p][4]), u5 = unpack2(acc[p][5]);
        float2 u6 = unpack2(acc[p][6]), u7 = unpack2(acc[p][7]);
#pragma unroll
        for (int half = 0; half < 2; half++) {
            int n = base + ty * 4 + 2 * p + half;
            if (n >= N_NODES) continue;
            float sn = __ldg(&snorm[n]);
            float a0 = half ? u0.y : u0.x, a1 = half ? u1.y : u1.x;
            float a2 = half ? u2.y : u2.x, a3 = half ? u3.y : u3.x;
            float a4 = half ? u4.y : u4.x, a5 = half ? u5.y : u5.x;
            float a6 = half ? u6.y : u6.x, a7 = half ? u7.y : u7.x;
            float4 oA, oB;
            oA.x = (a0 + bA.x) * sn; oA.y = (a1 + bA.y) * sn;
            oA.z = (a2 + bA.z) * sn; oA.w = (a3 + bA.w) * sn;
            oB.x = (a4 + bB.x) * sn; oB.y = (a5 + bB.y) * sn;
            oB.z = (a6 + bB.z) * sn; oB.w = (a7 + bB.w) * sn;
            *reinterpret_cast<float4*>(&g_h2[n * D + tx * 8])     = oA;
            *reinterpret_cast<float4*>(&g_h2[n * D + tx * 8 + 4]) = oB;
            s0 += oA.x; s1 += oA.y; s2 += oA.z; s3 += oA.w;
            s4 += oB.x; s5 += oB.y; s6 += oB.z; s7 += oB.w;
            q0 += oA.x * oA.x; q1 += oA.y * oA.y; q2 += oA.z * oA.z; q3 += oA.w * oA.w;
            q4 += oB.x * oB.x; q5 += oB.y * oB.y; q6 += oB.z * oB.z; q7 += oB.w * oB.w;
        }
    }
    int ob = tx * 8;
    atomicAdd(&sStats[ob + 0], s0); atomicAdd(&sStats[ob + 1], s1);
    atomicAdd(&sStats[ob + 2], s2); atomicAdd(&sStats[ob + 3], s3);
    atomicAdd(&sStats[ob + 4], s4); atomicAdd(&sStats[ob + 5], s5);
    atomicAdd(&sStats[ob + 6], s6); atomicAdd(&sStats[ob + 7], s7);
    atomicAdd(&sStats[D + ob + 0], q0); atomicAdd(&sStats[D + ob + 1], q1);
    atomicAdd(&sStats[D + ob + 2], q2); atomicAdd(&sStats[D + ob + 3], q3);
    atomicAdd(&sStats[D + ob + 4], q4); atomicAdd(&sStats[D + ob + 5], q5);
    atomicAdd(&sStats[D + ob + 6], q6); atomicAdd(&sStats[D + ob + 7], q7);
    __syncthreads();
    if (t < 2 * D) atomicAdd(&g_stats[t], sStats[t]);
}

// ---------------- K5: BN scale/shift ----------------
__global__ void k_bn(const float* __restrict__ gamma, const float* __restrict__ beta) {
    int f = threadIdx.x;
    if (f < D) {
        const float inv = 1.0f / (float)N_NODES;
        float mu = g_stats[f] * inv;
        float var = g_stats[D + f] * inv - mu * mu;
        float sc = gamma[f] * rsqrtf(var + 1e-5f);
        g_scale[f] = sc;
        g_shift[f] = beta[f] - mu * sc;
    }
}

// ---------------- K6: final elementwise ----------------
__global__ __launch_bounds__(256) void k_final(const float* __restrict__ h,
                                               float* __restrict__ out) {
    int i = blockIdx.x * 256 + threadIdx.x;
    const int NV = (N_NODES * D) / 4;
    if (i >= NV) return;
    int f4 = (i & 15) * 4;
    float4 v = reinterpret_cast<const float4*>(g_h2)[i];
    float4 hv = reinterpret_cast<const float4*>(h)[i];
    float4 sc = *reinterpret_cast<const float4*>(&g_scale[f4]);
    float4 sh = *reinterpret_cast<const float4*>(&g_shift[f4]);
    float4 o;
    o.x = hv.x + fmaxf(v.x * sc.x + sh.x, 0.0f);
    o.y = hv.y + fmaxf(v.y * sc.y + sh.y, 0.0f);
    o.z = hv.z + fmaxf(v.z * sc.z + sh.z, 0.0f);
    o.w = hv.w + fmaxf(v.w * sc.w + sh.w, 0.0f);
    reinterpret_cast<float4*>(out)[i] = o;
}

// ---------------- launch ----------------
extern "C" void kernel_launch(void* const* d_in, const int* in_sizes, int n_in,
                              void* d_out, int out_size) {
    const float* h     = (const float*)d_in[0];
    const float* eig   = (const float*)d_in[1];
    const float* snorm = (const float*)d_in[2];
    const int*   src   = (const int*)d_in[3];
    const int*   dst   = (const int*)d_in[4];
    const float* W1    = (const float*)d_in[5];
    const float* b1    = (const float*)d_in[6];
    const float* W2    = (const float*)d_in[7];
    const float* b2    = (const float*)d_in[8];
    const float* gamma = (const float*)d_in[9];
    const float* beta  = (const float*)d_in[10];
    float* out = (float*)d_out;

    const int EB = (N_EDGES + 255) / 256;
    const int NB1 = (N_NODES + 1023) / 1024;   // 98

    size_t smem1 = (size_t)(64 * WD1_S + 64 * HT_S) * sizeof(float);   // ~99.8KB
    size_t smem2 = (size_t)(64 * HC2_S + 64 * WD2_S) * sizeof(float);  // ~67KB
    cudaFuncSetAttribute(k_pretrans, cudaFuncAttributeMaxDynamicSharedMemorySize, (int)smem1);
    cudaFuncSetAttribute(k_post, cudaFuncAttributeMaxDynamicSharedMemorySize, (int)smem2);

    k_prep<<<(N_NODES + 255) / 256, 256>>>(W2);
    k_deg<<<EB, 256>>>(dst);
    k_pretrans<<<(N_NODES + 127) / 128, 256, smem1>>>(h, W1);
    k_scan1<<<NB1, 1024>>>();
    k_scan2<<<1, 128>>>(NB1);
    k_scan3<<<(N_NODES + 255) / 256, 256>>>();
    k_scatter<<<EB, 256>>>(src, dst, eig);
    k_gather<<<N_NODES / 8, 256>>>();

    k_post<<<(N_NODES + 127) / 128, 256, smem2>>>(h, snorm, b1, b2);
    k_bn<<<1, 64>>>(gamma, beta);
    k_final<<<(N_NODES * D / 4 + 255) / 256, 256>>>(h, out);
}

// round 13
// speedup vs baseline: 1.5633x; 1.5633x over previous
#include <cuda_runtime.h>
#include <math.h>

#define N_NODES 100000
#define N_EDGES 1250000
#define D 64
#define EPSF 1e-8f
#define NEG_INF __int_as_float(0xff800000)

// ---------------- scratch (static device memory; no allocation) ----------------
__device__ float g_A[N_NODES * D];      // h @ W1[:, :64].T
__device__ float g_B[N_NODES * D];      // h @ W1[:, 64:].T
__device__ float g_sumA[N_NODES * D];   // seg_sum over dst of A[src]
__device__ float g_maxA[N_NODES * D];   // seg_max over dst of A[src]
__device__ float g_sumwA[N_NODES * D];  // seg_sum over dst of eig*A[src] (raw)
__device__ float g_h2[N_NODES * D];     // posttrans output (pre-BN)
__device__ float g_absum[N_NODES];      // seg_sum |eig|
__device__ float g_sEig[N_NODES];       // seg_sum eig
__device__ float g_deg[N_NODES];        // degree (float)
__device__ float g_stats[2 * D];        // per-feature sum, sumsq of h2
__device__ float g_scale[D];            // BN scale
__device__ float g_shift[D];            // BN shift
__device__ float g_W2T[256 * D];        // W2 transposed: [k][o]
// CSR machinery
__device__ int g_degi[N_NODES];         // int degree
__device__ int g_start[N_NODES];        // CSR row start (exclusive scan)
__device__ int g_cursor[N_NODES];       // scatter cursors
__device__ int2 g_epack[N_EDGES];       // (src, eig bits) grouped by dst
__device__ int g_bsum[128];             // scan block sums

// ---------------- K0: prep (zero degi/stats + transpose W2) ----------------
__global__ __launch_bounds__(256) void k_prep(const float* __restrict__ W2) {
    int i = blockIdx.x * 256 + threadIdx.x;
    if (i < N_NODES) g_degi[i] = 0;
    if (i < 2 * D) g_stats[i] = 0.0f;
    if (i < D * 256) {            // i = o*256 + k
        int o = i >> 8, k = i & 255;
        g_W2T[k * D + o] = W2[i];
    }
}

// ---------------- K1: node pretrans  A,B = h @ [W1a|W1b].T ----------------
// 256 threads, 128 nodes/block. Thread tile: 8 nodes x 8 outputs (out dim 128).
// (Round-10 proven: 63.9us, issue=53.8%)
#define WT_S 132   // sWt row stride (float4-aligned; 4-way STS conflict at worst)
#define HT_S 129   // sHt row stride (conflict-free STS and LDS)
__global__ __launch_bounds__(256) void k_pretrans(const float* __restrict__ h,
                                                  const float* __restrict__ W1) {
    __shared__ __align__(16) float sWt[64 * WT_S]; // [k][o] o<64 -> A, o>=64 -> B
    __shared__ float sHt[64 * HT_S];               // [k][node_local]
    int t = threadIdx.x;
    int base = blockIdx.x * 128;

    for (int idx = t; idx < 64 * 128; idx += 256) {
        int o = idx >> 7, kk = idx & 127;
        float v = W1[idx];                 // W1 row-major [o][kk]
        if (kk < D) sWt[kk * WT_S + o] = v;
        else        sWt[(kk - D) * WT_S + o + D] = v;
    }
    for (int idx = t; idx < 128 * 64; idx += 256) {
        int nl = idx >> 6, k = idx & 63;
        int n = base + nl;
        sHt[k * HT_S + nl] = (n < N_NODES) ? h[n * D + k] : 0.0f;
    }
    __syncthreads();

    int tx = t & 15, ty = t >> 4;   // tx: 8 outputs each (128 total); ty: 8 nodes each
    float acc[8][8];
#pragma unroll
    for (int i = 0; i < 8; i++)
#pragma unroll
        for (int j = 0; j < 8; j++) acc[i][j] = 0.0f;

#pragma unroll 2
    for (int k = 0; k < 64; k++) {
        float4 b0 = *reinterpret_cast<float4*>(&sWt[k * WT_S + tx * 8]);
        float4 b1v = *reinterpret_cast<float4*>(&sWt[k * WT_S + tx * 8 + 4]);
#pragma unroll
        for (int i = 0; i < 8; i++) {
            float a = sHt[k * HT_S + ty * 8 + i];
            acc[i][0] += a * b0.x;  acc[i][1] += a * b0.y;
            acc[i][2] += a * b0.z;  acc[i][3] += a * b0.w;
            acc[i][4] += a * b1v.x; acc[i][5] += a * b1v.y;
            acc[i][6] += a * b1v.z; acc[i][7] += a * b1v.w;
        }
    }

#pragma unroll
    for (int i = 0; i < 8; i++) {
        int n = base + ty * 8 + i;
        if (n >= N_NODES) continue;
        float4 v0 = make_float4(acc[i][0], acc[i][1], acc[i][2], acc[i][3]);
        float4 v1 = make_float4(acc[i][4], acc[i][5], acc[i][6], acc[i][7]);
        if (tx < 8) {
            *reinterpret_cast<float4*>(&g_A[n * D + tx * 8])     = v0;
            *reinterpret_cast<float4*>(&g_A[n * D + tx * 8 + 4]) = v1;
        } else {
            int o = tx * 8 - D;
            *reinterpret_cast<float4*>(&g_B[n * D + o])     = v0;
            *reinterpret_cast<float4*>(&g_B[n * D + o + 4]) = v1;
        }
    }
}

// ---------------- CSR build ----------------
__global__ __launch_bounds__(256) void k_deg(const int* __restrict__ dst) {
    int e = blockIdx.x * 256 + threadIdx.x;
    if (e < N_EDGES) atomicAdd(&g_degi[__ldg(&dst[e])], 1);
}

__global__ __launch_bounds__(1024) void k_scan1() {
    __shared__ int wsum[32];
    int t = threadIdx.x;
    int lane = t & 31, wid = t >> 5;
    int n = blockIdx.x * 1024 + t;
    int v = (n < N_NODES) ? g_degi[n] : 0;
    int inc = v;
#pragma unroll
    for (int off = 1; off < 32; off <<= 1) {
        int y = __shfl_up_sync(0xffffffffu, inc, off);
        if (lane >= off) inc += y;
    }
    if (lane == 31) wsum[wid] = inc;
    __syncthreads();
    if (wid == 0) {
        int s = wsum[lane];
        int inc2 = s;
#pragma unroll
        for (int off = 1; off < 32; off <<= 1) {
            int y = __shfl_up_sync(0xffffffffu, inc2, off);
            if (lane >= off) inc2 += y;
        }
        wsum[lane] = inc2 - s;            // exclusive warp offset
        if (lane == 31) g_bsum[blockIdx.x] = inc2;   // block total
    }
    __syncthreads();
    if (n < N_NODES) g_start[n] = inc - v + wsum[wid];
}

__global__ __launch_bounds__(128) void k_scan2(int nblk) {
    __shared__ int s[128];
    int t = threadIdx.x;
    int v = (t < nblk) ? g_bsum[t] : 0;
    s[t] = v;
    __syncthreads();
#pragma unroll
    for (int off = 1; off < 128; off <<= 1) {
        int x = (t >= off) ? s[t - off] : 0;
        __syncthreads();
        s[t] += x;
        __syncthreads();
    }
    if (t < nblk) g_bsum[t] = s[t] - v;   // exclusive
}

__global__ __launch_bounds__(256) void k_scan3() {
    int n = blockIdx.x * 256 + threadIdx.x;
    if (n < N_NODES) {
        int st = g_start[n] + g_bsum[n >> 10];
        g_start[n] = st;
        g_cursor[n] = st;
    }
}

__global__ __launch_bounds__(256) void k_scatter(const int* __restrict__ src,
                                                 const int* __restrict__ dst,
                                                 const float* __restrict__ eig) {
    int e = blockIdx.x * 256 + threadIdx.x;
    if (e < N_EDGES) {
        int d = __ldg(&dst[e]);
        int pos = atomicAdd(&g_cursor[d], 1);
        g_epack[pos] = make_int2(__ldg(&src[e]), __float_as_int(__ldg(&eig[e])));
    }
}

// ---------------- K2: CSR gather (one warp per node, unroll-2 pipeline) ----------------
__global__ __launch_bounds__(256) void k_gather() {
    int t = threadIdx.x;
    int n = blockIdx.x * 8 + (t >> 5);     // grid*8 == N_NODES exactly
    int lane = t & 31;
    int grp = lane >> 4;                   // 0/1
    int c = lane & 15;                     // feature quad

    int st = g_start[n];
    int deg = g_degi[n];
    int en = st + deg;

    float4 sum = make_float4(0.f, 0.f, 0.f, 0.f);
    float4 sw  = make_float4(0.f, 0.f, 0.f, 0.f);
    float4 mx  = make_float4(NEG_INF, NEG_INF, NEG_INF, NEG_INF);
    float ab = 0.f, sE = 0.f;

    int i = st + grp;
    for (; i + 2 < en; i += 4) {           // 2 edges in flight per group
        int2 pa = __ldg(&g_epack[i]);
        int2 pb = __ldg(&g_epack[i + 2]);
        float4 aa = *reinterpret_cast<const float4*>(&g_A[pa.x * D + c * 4]);
        float4 abv = *reinterpret_cast<const float4*>(&g_A[pb.x * D + c * 4]);
        float wa = __int_as_float(pa.y), wb = __int_as_float(pb.y);
        sum.x += aa.x + abv.x; sum.y += aa.y + abv.y;
        sum.z += aa.z + abv.z; sum.w += aa.w + abv.w;
        mx.x = fmaxf(mx.x, fmaxf(aa.x, abv.x)); mx.y = fmaxf(mx.y, fmaxf(aa.y, abv.y));
        mx.z = fmaxf(mx.z, fmaxf(aa.z, abv.z)); mx.w = fmaxf(mx.w, fmaxf(aa.w, abv.w));
        sw.x += wa * aa.x + wb * abv.x; sw.y += wa * aa.y + wb * abv.y;
        sw.z += wa * aa.z + wb * abv.z; sw.w += wa * aa.w + wb * abv.w;
        ab += fabsf(wa) + fabsf(wb); sE += wa + wb;
    }
    if (i < en) {
        int2 p = __ldg(&g_epack[i]);
        float w = __int_as_float(p.y);
        float4 a = *reinterpret_cast<const float4*>(&g_A[p.x * D + c * 4]);
        sum.x += a.x; sum.y += a.y; sum.z += a.z; sum.w += a.w;
        mx.x = fmaxf(mx.x, a.x); mx.y = fmaxf(mx.y, a.y);
        mx.z = fmaxf(mx.z, a.z); mx.w = fmaxf(mx.w, a.w);
        sw.x += w * a.x; sw.y += w * a.y; sw.z += w * a.z; sw.w += w * a.w;
        ab += fabsf(w); sE += w;
    }

    sum.x += __shfl_down_sync(0xffffffffu, sum.x, 16);
    sum.y += __shfl_down_sync(0xffffffffu, sum.y, 16);
    sum.z += __shfl_down_sync(0xffffffffu, sum.z, 16);
    sum.w += __shfl_down_sync(0xffffffffu, sum.w, 16);
    mx.x = fmaxf(mx.x, __shfl_down_sync(0xffffffffu, mx.x, 16));
    mx.y = fmaxf(mx.y, __shfl_down_sync(0xffffffffu, mx.y, 16));
    mx.z = fmaxf(mx.z, __shfl_down_sync(0xffffffffu, mx.z, 16));
    mx.w = fmaxf(mx.w, __shfl_down_sync(0xffffffffu, mx.w, 16));
    sw.x += __shfl_down_sync(0xffffffffu, sw.x, 16);
    sw.y += __shfl_down_sync(0xffffffffu, sw.y, 16);
    sw.z += __shfl_down_sync(0xffffffffu, sw.z, 16);
    sw.w += __shfl_down_sync(0xffffffffu, sw.w, 16);
    ab += __shfl_down_sync(0xffffffffu, ab, 16);
    sE += __shfl_down_sync(0xffffffffu, sE, 16);

    if (grp == 0) {
        int o = n * D + c * 4;
        *reinterpret_cast<float4*>(&g_sumA[o])  = sum;
        *reinterpret_cast<float4*>(&g_maxA[o])  = mx;
        *reinterpret_cast<float4*>(&g_sumwA[o]) = sw;
        if (c == 0) {
            g_deg[n] = (float)deg;
            g_absum[n] = ab;
            g_sEig[n] = sE;
        }
    }
}

// ---------------- K4: node posttrans GEMM + BN partial stats ----------------
// 256 threads, 256 nodes/block. hc built chunk-by-chunk ([h|mean|max|dir]).
// Thread tile: 8 nodes x 8 outputs (mirrors proven k_pretrans structure).
#define HC_S 67   // a-load stride: 8*67=536 ≡ 24 mod 32 -> 4 distinct banks across ty
__global__ __launch_bounds__(256) void k_post(const float* __restrict__ h,
                                              const float* __restrict__ snorm,
                                              const float* __restrict__ b1,
                                              const float* __restrict__ b2) {
    extern __shared__ float dsm[];
    float* sHC = dsm;                       // [256 nodes][HC_S] one chunk (~68.6KB)
    float* sW2 = dsm + 256 * HC_S;          // [k][o] one chunk of W2T (16KB)
    __shared__ float sStats[2 * D];
    __shared__ float sDeg[256], sAb[256], sSE[256];

    int t = threadIdx.x;
    int base = blockIdx.x * 256;

    {
        int n = base + t;
        float deg = 0.0f, ab = EPSF, sE = 0.0f;
        if (n < N_NODES) { deg = g_deg[n]; ab = g_absum[n] + EPSF; sE = g_sEig[n]; }
        sDeg[t] = deg; sAb[t] = ab; sSE[t] = sE;
    }
    if (t < 2 * D) sStats[t] = 0.0f;

    int f = t & 63;
    int quarter = t >> 6;          // 0..3
    float b1f = __ldg(&b1[f]);

    int tx = t & 7, ty = t >> 3;   // tx: 8 outputs each (64); ty: 0..31, 8 nodes each (256)
    float acc[8][8];
#pragma unroll
    for (int i = 0; i < 8; i++)
#pragma unroll
        for (int j = 0; j < 8; j++) acc[i][j] = 0.0f;

#pragma unroll
    for (int cch = 0; cch < 4; cch++) {
        __syncthreads();   // previous chunk's GEMM reads done; sDeg/sStats init done
        // stage W2T chunk: 4096 floats, coalesced float4
#pragma unroll
        for (int i = t * 4; i < 4096; i += 1024)
            *reinterpret_cast<float4*>(&sW2[i]) =
                *reinterpret_cast<const float4*>(&g_W2T[cch * 4096 + i]);
        // build hc chunk [256 nodes][64 feats]
        for (int r = 0; r < 64; r++) {
            int nl = quarter + r * 4;
            int n = base + nl;
            float v = 0.0f;
            if (n < N_NODES) {
                int o = n * D + f;
                if (cch == 0) {
                    v = h[o];
                } else if (cch == 1) {
                    float deg = sDeg[nl];
                    v = (g_sumA[o] + deg * (g_B[o] + b1f)) / fmaxf(deg, 1.0f);
                } else if (cch == 2) {
                    v = (sDeg[nl] > 0.0f) ? (g_maxA[o] + g_B[o] + b1f) : 0.0f;
                } else {
                    float sE = sSE[nl], ab = sAb[nl];
                    v = fabsf((g_sumwA[o] + sE * (g_B[o] + b1f)) / ab - (sE / ab) * h[o]);
                }
            }
            sHC[nl * HC_S + f] = v;
        }
        __syncthreads();
        // GEMM accumulate over this chunk's 64 k
#pragma unroll 2
        for (int k = 0; k < 64; k++) {
            float4 b0 = *reinterpret_cast<float4*>(&sW2[k * 64 + tx * 8]);
            float4 b1v = *reinterpret_cast<float4*>(&sW2[k * 64 + tx * 8 + 4]);
#pragma unroll
            for (int i = 0; i < 8; i++) {
                float a = sHC[(ty * 8 + i) * HC_S + k];
                acc[i][0] += a * b0.x;  acc[i][1] += a * b0.y;
                acc[i][2] += a * b0.z;  acc[i][3] += a * b0.w;
                acc[i][4] += a * b1v.x; acc[i][5] += a * b1v.y;
                acc[i][6] += a * b1v.z; acc[i][7] += a * b1v.w;
            }
        }
    }

    // epilogue: bias, snorm, write h2, BN partial stats
    float4 bA = *reinterpret_cast<const float4*>(&b2[tx * 8]);
    float4 bB = *reinterpret_cast<const float4*>(&b2[tx * 8 + 4]);
    float s0 = 0, s1 = 0, s2 = 0, s3 = 0, s4 = 0, s5 = 0, s6 = 0, s7 = 0;
    float q0 = 0, q1 = 0, q2 = 0, q3 = 0, q4 = 0, q5 = 0, q6 = 0, q7 = 0;
#pragma unroll
    for (int i = 0; i < 8; i++) {
        int n = base + ty * 8 + i;
        if (n >= N_NODES) continue;
        float sn = __ldg(&snorm[n]);
        float4 oA, oB;
        oA.x = (acc[i][0] + bA.x) * sn; oA.y = (acc[i][1] + bA.y) * sn;
        oA.z = (acc[i][2] + bA.z) * sn; oA.w = (acc[i][3] + bA.w) * sn;
        oB.x = (acc[i][4] + bB.x) * sn; oB.y = (acc[i][5] + bB.y) * sn;
        oB.z = (acc[i][6] + bB.z) * sn; oB.w = (acc[i][7] + bB.w) * sn;
        *reinterpret_cast<float4*>(&g_h2[n * D + tx * 8])     = oA;
        *reinterpret_cast<float4*>(&g_h2[n * D + tx * 8 + 4]) = oB;
        s0 += oA.x; s1 += oA.y; s2 += oA.z; s3 += oA.w;
        s4 += oB.x; s5 += oB.y; s6 += oB.z; s7 += oB.w;
        q0 += oA.x * oA.x; q1 += oA.y * oA.y; q2 += oA.z * oA.z; q3 += oA.w * oA.w;
        q4 += oB.x * oB.x; q5 += oB.y * oB.y; q6 += oB.z * oB.z; q7 += oB.w * oB.w;
    }
    int ob = tx * 8;
    atomicAdd(&sStats[ob + 0], s0); atomicAdd(&sStats[ob + 1], s1);
    atomicAdd(&sStats[ob + 2], s2); atomicAdd(&sStats[ob + 3], s3);
    atomicAdd(&sStats[ob + 4], s4); atomicAdd(&sStats[ob + 5], s5);
    atomicAdd(&sStats[ob + 6], s6); atomicAdd(&sStats[ob + 7], s7);
    atomicAdd(&sStats[D + ob + 0], q0); atomicAdd(&sStats[D + ob + 1], q1);
    atomicAdd(&sStats[D + ob + 2], q2); atomicAdd(&sStats[D + ob + 3], q3);
    atomicAdd(&sStats[D + ob + 4], q4); atomicAdd(&sStats[D + ob + 5], q5);
    atomicAdd(&sStats[D + ob + 6], q6); atomicAdd(&sStats[D + ob + 7], q7);
    __syncthreads();
    if (t < 2 * D) atomicAdd(&g_stats[t], sStats[t]);
}

// ---------------- K5: BN scale/shift ----------------
__global__ void k_bn(const float* __restrict__ gamma, const float* __restrict__ beta) {
    int f = threadIdx.x;
    if (f < D) {
        const float inv = 1.0f / (float)N_NODES;
        float mu = g_stats[f] * inv;
        float var = g_stats[D + f] * inv - mu * mu;
        float sc = gamma[f] * rsqrtf(var + 1e-5f);
        g_scale[f] = sc;
        g_shift[f] = beta[f] - mu * sc;
    }
}

// ---------------- K6: final elementwise ----------------
__global__ __launch_bounds__(256) void k_final(const float* __restrict__ h,
                                               float* __restrict__ out) {
    int i = blockIdx.x * 256 + threadIdx.x;
    const int NV = (N_NODES * D) / 4;
    if (i >= NV) return;
    int f4 = (i & 15) * 4;
    float4 v = reinterpret_cast<const float4*>(g_h2)[i];
    float4 hv = reinterpret_cast<const float4*>(h)[i];
    float4 sc = *reinterpret_cast<const float4*>(&g_scale[f4]);
    float4 sh = *reinterpret_cast<const float4*>(&g_shift[f4]);
    float4 o;
    o.x = hv.x + fmaxf(v.x * sc.x + sh.x, 0.0f);
    o.y = hv.y + fmaxf(v.y * sc.y + sh.y, 0.0f);
    o.z = hv.z + fmaxf(v.z * sc.z + sh.z, 0.0f);
    o.w = hv.w + fmaxf(v.w * sc.w + sh.w, 0.0f);
    reinterpret_cast<float4*>(out)[i] = o;
}

// ---------------- launch ----------------
extern "C" void kernel_launch(void* const* d_in, const int* in_sizes, int n_in,
                              void* d_out, int out_size) {
    const float* h     = (const float*)d_in[0];
    const float* eig   = (const float*)d_in[1];
    const float* snorm = (const float*)d_in[2];
    const int*   src   = (const int*)d_in[3];
    const int*   dst   = (const int*)d_in[4];
    const float* W1    = (const float*)d_in[5];
    const float* b1    = (const float*)d_in[6];
    const float* W2    = (const float*)d_in[7];
    const float* b2    = (const float*)d_in[8];
    const float* gamma = (const float*)d_in[9];
    const float* beta  = (const float*)d_in[10];
    float* out = (float*)d_out;

    const int EB = (N_EDGES + 255) / 256;
    const int NB1 = (N_NODES + 1023) / 1024;   // 98

    size_t smem2 = (size_t)(256 * HC_S + 64 * 64) * sizeof(float);  // ~85KB
    cudaFuncSetAttribute(k_post, cudaFuncAttributeMaxDynamicSharedMemorySize, (int)smem2);

    k_prep<<<(N_NODES + 255) / 256, 256>>>(W2);
    k_deg<<<EB, 256>>>(dst);
    k_pretrans<<<(N_NODES + 127) / 128, 256>>>(h, W1);
    k_scan1<<<NB1, 1024>>>();
    k_scan2<<<1, 128>>>(NB1);
    k_scan3<<<(N_NODES + 255) / 256, 256>>>();
    k_scatter<<<EB, 256>>>(src, dst, eig);
    k_gather<<<N_NODES / 8, 256>>>();

    k_post<<<(N_NODES + 255) / 256, 256, smem2>>>(h, snorm, b1, b2);
    k_bn<<<1, 64>>>(gamma, beta);
    k_final<<<(N_NODES * D / 4 + 255) / 256, 256>>>(h, out);
}

// round 15
// speedup vs baseline: 1.9384x; 1.2399x over previous
#include <cuda_runtime.h>
#include <math.h>

#define N_NODES 100000
#define N_EDGES 1250000
#define D 64
#define EPSF 1e-8f
#define NEG_INF __int_as_float(0xff800000)

// ---------------- scratch (static device memory; no allocation) ----------------
__device__ float g_A[N_NODES * D];      // h @ W1[:, :64].T
__device__ float g_B[N_NODES * D];      // h @ W1[:, 64:].T
__device__ float g_sumA[N_NODES * D];   // seg_sum over dst of A[src]
__device__ float g_maxA[N_NODES * D];   // seg_max over dst of A[src]
__device__ float g_sumwA[N_NODES * D];  // seg_sum over dst of eig*A[src] (raw)
__device__ float g_h2[N_NODES * D];     // posttrans output (pre-BN)
__device__ float g_absum[N_NODES];      // seg_sum |eig|
__device__ float g_sEig[N_NODES];       // seg_sum eig
__device__ float g_deg[N_NODES];        // degree (float)
__device__ float g_stats[2 * D];        // per-feature sum, sumsq of h2
__device__ float g_scale[D];            // BN scale
__device__ float g_shift[D];            // BN shift
__device__ float g_W2T[256 * D];        // W2 transposed: [k][o]
// CSR machinery
__device__ int g_degi[N_NODES];         // int degree
__device__ int g_start[N_NODES];        // CSR row start (exclusive scan)
__device__ int g_cursor[N_NODES];       // scatter cursors
__device__ int2 g_epack[N_EDGES];       // (src, eig bits) grouped by dst
__device__ int g_bsum[128];             // scan block sums

// ---------------- K0: prep (zero degi/stats + transpose W2) ----------------
__global__ __launch_bounds__(256) void k_prep(const float* __restrict__ W2) {
    int i = blockIdx.x * 256 + threadIdx.x;
    if (i < N_NODES) g_degi[i] = 0;
    if (i < 2 * D) g_stats[i] = 0.0f;
    if (i < D * 256) {            // i = o*256 + k
        int o = i >> 8, k = i & 255;
        g_W2T[k * D + o] = W2[i];
    }
}

// ---------------- K1: node pretrans  A,B = h @ [W1a|W1b].T ----------------
// 256 threads, 128 nodes/block. Thread tile: 8 nodes x 8 outputs (out dim 128).
// (Round-10 proven: 63.9us, issue=53.8%)
#define WT_S 132   // sWt row stride (float4-aligned; 4-way STS conflict at worst)
#define HT_S 129   // sHt row stride (conflict-free STS and LDS)
__global__ __launch_bounds__(256) void k_pretrans(const float* __restrict__ h,
                                                  const float* __restrict__ W1) {
    __shared__ __align__(16) float sWt[64 * WT_S]; // [k][o] o<64 -> A, o>=64 -> B
    __shared__ float sHt[64 * HT_S];               // [k][node_local]
    int t = threadIdx.x;
    int base = blockIdx.x * 128;

    for (int idx = t; idx < 64 * 128; idx += 256) {
        int o = idx >> 7, kk = idx & 127;
        float v = W1[idx];                 // W1 row-major [o][kk]
        if (kk < D) sWt[kk * WT_S + o] = v;
        else        sWt[(kk - D) * WT_S + o + D] = v;
    }
    for (int idx = t; idx < 128 * 64; idx += 256) {
        int nl = idx >> 6, k = idx & 63;
        int n = base + nl;
        sHt[k * HT_S + nl] = (n < N_NODES) ? h[n * D + k] : 0.0f;
    }
    __syncthreads();

    int tx = t & 15, ty = t >> 4;   // tx: 8 outputs each (128 total); ty: 8 nodes each
    float acc[8][8];
#pragma unroll
    for (int i = 0; i < 8; i++)
#pragma unroll
        for (int j = 0; j < 8; j++) acc[i][j] = 0.0f;

#pragma unroll 2
    for (int k = 0; k < 64; k++) {
        float4 b0 = *reinterpret_cast<float4*>(&sWt[k * WT_S + tx * 8]);
        float4 b1v = *reinterpret_cast<float4*>(&sWt[k * WT_S + tx * 8 + 4]);
#pragma unroll
        for (int i = 0; i < 8; i++) {
            float a = sHt[k * HT_S + ty * 8 + i];
            acc[i][0] += a * b0.x;  acc[i][1] += a * b0.y;
            acc[i][2] += a * b0.z;  acc[i][3] += a * b0.w;
            acc[i][4] += a * b1v.x; acc[i][5] += a * b1v.y;
            acc[i][6] += a * b1v.z; acc[i][7] += a * b1v.w;
        }
    }

#pragma unroll
    for (int i = 0; i < 8; i++) {
        int n = base + ty * 8 + i;
        if (n >= N_NODES) continue;
        float4 v0 = make_float4(acc[i][0], acc[i][1], acc[i][2], acc[i][3]);
        float4 v1 = make_float4(acc[i][4], acc[i][5], acc[i][6], acc[i][7]);
        if (tx < 8) {
            *reinterpret_cast<float4*>(&g_A[n * D + tx * 8])     = v0;
            *reinterpret_cast<float4*>(&g_A[n * D + tx * 8 + 4]) = v1;
        } else {
            int o = tx * 8 - D;
            *reinterpret_cast<float4*>(&g_B[n * D + o])     = v0;
            *reinterpret_cast<float4*>(&g_B[n * D + o + 4]) = v1;
        }
    }
}

// ---------------- CSR build ----------------
__global__ __launch_bounds__(256) void k_deg(const int* __restrict__ dst) {
    int e = blockIdx.x * 256 + threadIdx.x;
    if (e < N_EDGES) atomicAdd(&g_degi[__ldg(&dst[e])], 1);
}

__global__ __launch_bounds__(1024) void k_scan1() {
    __shared__ int wsum[32];
    int t = threadIdx.x;
    int lane = t & 31, wid = t >> 5;
    int n = blockIdx.x * 1024 + t;
    int v = (n < N_NODES) ? g_degi[n] : 0;
    int inc = v;
#pragma unroll
    for (int off = 1; off < 32; off <<= 1) {
        int y = __shfl_up_sync(0xffffffffu, inc, off);
        if (lane >= off) inc += y;
    }
    if (lane == 31) wsum[wid] = inc;
    __syncthreads();
    if (wid == 0) {
        int s = wsum[lane];
        int inc2 = s;
#pragma unroll
        for (int off = 1; off < 32; off <<= 1) {
            int y = __shfl_up_sync(0xffffffffu, inc2, off);
            if (lane >= off) inc2 += y;
        }
        wsum[lane] = inc2 - s;            // exclusive warp offset
        if (lane == 31) g_bsum[blockIdx.x] = inc2;   // block total
    }
    __syncthreads();
    if (n < N_NODES) g_start[n] = inc - v + wsum[wid];
}

__global__ __launch_bounds__(128) void k_scan2(int nblk) {
    __shared__ int s[128];
    int t = threadIdx.x;
    int v = (t < nblk) ? g_bsum[t] : 0;
    s[t] = v;
    __syncthreads();
#pragma unroll
    for (int off = 1; off < 128; off <<= 1) {
        int x = (t >= off) ? s[t - off] : 0;
        __syncthreads();
        s[t] += x;
        __syncthreads();
    }
    if (t < nblk) g_bsum[t] = s[t] - v;   // exclusive
}

__global__ __launch_bounds__(256) void k_scan3() {
    int n = blockIdx.x * 256 + threadIdx.x;
    if (n < N_NODES) {
        int st = g_start[n] + g_bsum[n >> 10];
        g_start[n] = st;
        g_cursor[n] = st;
    }
}

__global__ __launch_bounds__(256) void k_scatter(const int* __restrict__ src,
                                                 const int* __restrict__ dst,
                                                 const float* __restrict__ eig) {
    int e = blockIdx.x * 256 + threadIdx.x;
    if (e < N_EDGES) {
        int d = __ldg(&dst[e]);
        int pos = atomicAdd(&g_cursor[d], 1);
        g_epack[pos] = make_int2(__ldg(&src[e]), __float_as_int(__ldg(&eig[e])));
    }
}

// ---------------- K2: CSR gather (one warp per node, unroll-2 pipeline) ----------------
__global__ __launch_bounds__(256) void k_gather() {
    int t = threadIdx.x;
    int n = blockIdx.x * 8 + (t >> 5);     // grid*8 == N_NODES exactly
    int lane = t & 31;
    int grp = lane >> 4;                   // 0/1
    int c = lane & 15;                     // feature quad

    int st = g_start[n];
    int deg = g_degi[n];
    int en = st + deg;

    float4 sum = make_float4(0.f, 0.f, 0.f, 0.f);
    float4 sw  = make_float4(0.f, 0.f, 0.f, 0.f);
    float4 mx  = make_float4(NEG_INF, NEG_INF, NEG_INF, NEG_INF);
    float ab = 0.f, sE = 0.f;

    int i = st + grp;
    for (; i + 2 < en; i += 4) {           // 2 edges in flight per group
        int2 pa = __ldg(&g_epack[i]);
        int2 pb = __ldg(&g_epack[i + 2]);
        float4 aa = *reinterpret_cast<const float4*>(&g_A[pa.x * D + c * 4]);
        float4 abv = *reinterpret_cast<const float4*>(&g_A[pb.x * D + c * 4]);
        float wa = __int_as_float(pa.y), wb = __int_as_float(pb.y);
        sum.x += aa.x + abv.x; sum.y += aa.y + abv.y;
        sum.z += aa.z + abv.z; sum.w += aa.w + abv.w;
        mx.x = fmaxf(mx.x, fmaxf(aa.x, abv.x)); mx.y = fmaxf(mx.y, fmaxf(aa.y, abv.y));
        mx.z = fmaxf(mx.z, fmaxf(aa.z, abv.z)); mx.w = fmaxf(mx.w, fmaxf(aa.w, abv.w));
        sw.x += wa * aa.x + wb * abv.x; sw.y += wa * aa.y + wb * abv.y;
        sw.z += wa * aa.z + wb * abv.z; sw.w += wa * aa.w + wb * abv.w;
        ab += fabsf(wa) + fabsf(wb); sE += wa + wb;
    }
    if (i < en) {
        int2 p = __ldg(&g_epack[i]);
        float w = __int_as_float(p.y);
        float4 a = *reinterpret_cast<const float4*>(&g_A[p.x * D + c * 4]);
        sum.x += a.x; sum.y += a.y; sum.z += a.z; sum.w += a.w;
        mx.x = fmaxf(mx.x, a.x); mx.y = fmaxf(mx.y, a.y);
        mx.z = fmaxf(mx.z, a.z); mx.w = fmaxf(mx.w, a.w);
        sw.x += w * a.x; sw.y += w * a.y; sw.z += w * a.z; sw.w += w * a.w;
        ab += fabsf(w); sE += w;
    }

    sum.x += __shfl_down_sync(0xffffffffu, sum.x, 16);
    sum.y += __shfl_down_sync(0xffffffffu, sum.y, 16);
    sum.z += __shfl_down_sync(0xffffffffu, sum.z, 16);
    sum.w += __shfl_down_sync(0xffffffffu, sum.w, 16);
    mx.x = fmaxf(mx.x, __shfl_down_sync(0xffffffffu, mx.x, 16));
    mx.y = fmaxf(mx.y, __shfl_down_sync(0xffffffffu, mx.y, 16));
    mx.z = fmaxf(mx.z, __shfl_down_sync(0xffffffffu, mx.z, 16));
    mx.w = fmaxf(mx.w, __shfl_down_sync(0xffffffffu, mx.w, 16));
    sw.x += __shfl_down_sync(0xffffffffu, sw.x, 16);
    sw.y += __shfl_down_sync(0xffffffffu, sw.y, 16);
    sw.z += __shfl_down_sync(0xffffffffu, sw.z, 16);
    sw.w += __shfl_down_sync(0xffffffffu, sw.w, 16);
    ab += __shfl_down_sync(0xffffffffu, ab, 16);
    sE += __shfl_down_sync(0xffffffffu, sE, 16);

    if (grp == 0) {
        int o = n * D + c * 4;
        *reinterpret_cast<float4*>(&g_sumA[o])  = sum;
        *reinterpret_cast<float4*>(&g_maxA[o])  = mx;
        *reinterpret_cast<float4*>(&g_sumwA[o]) = sw;
        if (c == 0) {
            g_deg[n] = (float)deg;
            g_absum[n] = ab;
            g_sEig[n] = sE;
        }
    }
}

// ---------------- K4: node posttrans GEMM + BN partial stats ----------------
// 256 threads, 128 nodes/block (Round-9 proven config of the 404us run).
#define HC_S 66
__global__ __launch_bounds__(256) void k_post(const float* __restrict__ h,
                                              const float* __restrict__ snorm,
                                              const float* __restrict__ b1,
                                              const float* __restrict__ b2) {
    __shared__ float sHC[128 * HC_S];            // [node][k] one chunk
    __shared__ __align__(16) float sW2[64 * 64]; // [k][o] one chunk of W2T
    __shared__ float sStats[2 * D];
    __shared__ float sDeg[128], sAb[128], sSE[128];

    int t = threadIdx.x;
    int base = blockIdx.x * 128;

    if (t < 128) {
        int n = base + t;
        float deg = 0.0f, ab = EPSF, sE = 0.0f;
        if (n < N_NODES) { deg = g_deg[n]; ab = g_absum[n] + EPSF; sE = g_sEig[n]; }
        sDeg[t] = deg; sAb[t] = ab; sSE[t] = sE;
        sStats[t] = 0.0f;
    }

    int f = t & 63;
    int quarter = t >> 6;          // 0..3
    float b1f = __ldg(&b1[f]);

    int tx = t & 7, ty = t >> 3;   // tx: 8 outputs each; ty: 0..31, 4 nodes each
    float acc[4][8];
#pragma unroll
    for (int i = 0; i < 4; i++)
#pragma unroll
        for (int j = 0; j < 8; j++) acc[i][j] = 0.0f;

#pragma unroll
    for (int cch = 0; cch < 4; cch++) {
        __syncthreads();
#pragma unroll
        for (int i = t * 4; i < 4096; i += 1024)
            *reinterpret_cast<float4*>(&sW2[i]) =
                *reinterpret_cast<const float4*>(&g_W2T[cch * 4096 + i]);
        for (int r = 0; r < 32; r++) {
            int nl = quarter + r * 4;
            int n = base + nl;
            float v = 0.0f;
            if (n < N_NODES) {
                int o = n * D + f;
                if (cch == 0) {
                    v = h[o];
                } else if (cch == 1) {
                    float deg = sDeg[nl];
                    v = (g_sumA[o] + deg * (g_B[o] + b1f)) / fmaxf(deg, 1.0f);
                } else if (cch == 2) {
                    v = (sDeg[nl] > 0.0f) ? (g_maxA[o] + g_B[o] + b1f) : 0.0f;
                } else {
                    float sE = sSE[nl], ab = sAb[nl];
                    v = fabsf((g_sumwA[o] + sE * (g_B[o] + b1f)) / ab - (sE / ab) * h[o]);
                }
            }
            sHC[nl * HC_S + f] = v;
        }
        __syncthreads();
#pragma unroll 4
        for (int k = 0; k < 64; k++) {
            float4 b0 = *reinterpret_cast<float4*>(&sW2[k * 64 + tx * 8]);
            float4 b1v = *reinterpret_cast<float4*>(&sW2[k * 64 + tx * 8 + 4]);
#pragma unroll
            for (int i = 0; i < 4; i++) {
                float a = sHC[(ty * 4 + i) * HC_S + k];
                acc[i][0] += a * b0.x;  acc[i][1] += a * b0.y;
                acc[i][2] += a * b0.z;  acc[i][3] += a * b0.w;
                acc[i][4] += a * b1v.x; acc[i][5] += a * b1v.y;
                acc[i][6] += a * b1v.z; acc[i][7] += a * b1v.w;
            }
        }
    }

    float4 bA = *reinterpret_cast<const float4*>(&b2[tx * 8]);
    float4 bB = *reinterpret_cast<const float4*>(&b2[tx * 8 + 4]);
    float s0 = 0, s1 = 0, s2 = 0, s3 = 0, s4 = 0, s5 = 0, s6 = 0, s7 = 0;
    float q0 = 0, q1 = 0, q2 = 0, q3 = 0, q4 = 0, q5 = 0, q6 = 0, q7 = 0;
#pragma unroll
    for (int i = 0; i < 4; i++) {
        int n = base + ty * 4 + i;
        if (n >= N_NODES) continue;
        float sn = __ldg(&snorm[n]);
        float4 oA, oB;
        oA.x = (acc[i][0] + bA.x) * sn; oA.y = (acc[i][1] + bA.y) * sn;
        oA.z = (acc[i][2] + bA.z) * sn; oA.w = (acc[i][3] + bA.w) * sn;
        oB.x = (acc[i][4] + bB.x) * sn; oB.y = (acc[i][5] + bB.y) * sn;
        oB.z = (acc[i][6] + bB.z) * sn; oB.w = (acc[i][7] + bB.w) * sn;
        *reinterpret_cast<float4*>(&g_h2[n * D + tx * 8])     = oA;
        *reinterpret_cast<float4*>(&g_h2[n * D + tx * 8 + 4]) = oB;
        s0 += oA.x; s1 += oA.y; s2 += oA.z; s3 += oA.w;
        s4 += oB.x; s5 += oB.y; s6 += oB.z; s7 += oB.w;
        q0 += oA.x * oA.x; q1 += oA.y * oA.y; q2 += oA.z * oA.z; q3 += oA.w * oA.w;
        q4 += oB.x * oB.x; q5 += oB.y * oB.y; q6 += oB.z * oB.z; q7 += oB.w * oB.w;
    }
    int ob = tx * 8;
    atomicAdd(&sStats[ob + 0], s0); atomicAdd(&sStats[ob + 1], s1);
    atomicAdd(&sStats[ob + 2], s2); atomicAdd(&sStats[ob + 3], s3);
    atomicAdd(&sStats[ob + 4], s4); atomicAdd(&sStats[ob + 5], s5);
    atomicAdd(&sStats[ob + 6], s6); atomicAdd(&sStats[ob + 7], s7);
    atomicAdd(&sStats[D + ob + 0], q0); atomicAdd(&sStats[D + ob + 1], q1);
    atomicAdd(&sStats[D + ob + 2], q2); atomicAdd(&sStats[D + ob + 3], q3);
    atomicAdd(&sStats[D + ob + 4], q4); atomicAdd(&sStats[D + ob + 5], q5);
    atomicAdd(&sStats[D + ob + 6], q6); atomicAdd(&sStats[D + ob + 7], q7);
    __syncthreads();
    if (t < 2 * D) atomicAdd(&g_stats[t], sStats[t]);
}

// ---------------- K5: BN scale/shift ----------------
__global__ void k_bn(const float* __restrict__ gamma, const float* __restrict__ beta) {
    int f = threadIdx.x;
    if (f < D) {
        const float inv = 1.0f / (float)N_NODES;
        float mu = g_stats[f] * inv;
        float var = g_stats[D + f] * inv - mu * mu;
        float sc = gamma[f] * rsqrtf(var + 1e-5f);
        g_scale[f] = sc;
        g_shift[f] = beta[f] - mu * sc;
    }
}

// ---------------- K6: final elementwise ----------------
__global__ __launch_bounds__(256) void k_final(const float* __restrict__ h,
                                               float* __restrict__ out) {
    int i = blockIdx.x * 256 + threadIdx.x;
    const int NV = (N_NODES * D) / 4;
    if (i >= NV) return;
    int f4 = (i & 15) * 4;
    float4 v = reinterpret_cast<const float4*>(g_h2)[i];
    float4 hv = reinterpret_cast<const float4*>(h)[i];
    float4 sc = *reinterpret_cast<const float4*>(&g_scale[f4]);
    float4 sh = *reinterpret_cast<const float4*>(&g_shift[f4]);
    float4 o;
    o.x = hv.x + fmaxf(v.x * sc.x + sh.x, 0.0f);
    o.y = hv.y + fmaxf(v.y * sc.y + sh.y, 0.0f);
    o.z = hv.z + fmaxf(v.z * sc.z + sh.z, 0.0f);
    o.w = hv.w + fmaxf(v.w * sc.w + sh.w, 0.0f);
    reinterpret_cast<float4*>(out)[i] = o;
}

// ---------------- launch ----------------
extern "C" void kernel_launch(void* const* d_in, const int* in_sizes, int n_in,
                              void* d_out, int out_size) {
    const float* h     = (const float*)d_in[0];
    const float* eig   = (const float*)d_in[1];
    const float* snorm = (const float*)d_in[2];
    const int*   src   = (const int*)d_in[3];
    const int*   dst   = (const int*)d_in[4];
    const float* W1    = (const float*)d_in[5];
    const float* b1    = (const float*)d_in[6];
    const float* W2    = (const float*)d_in[7];
    const float* b2    = (const float*)d_in[8];
    const float* gamma = (const float*)d_in[9];
    const float* beta  = (const float*)d_in[10];
    float* out = (float*)d_out;

    const int EB = (N_EDGES + 255) / 256;
    const int NB1 = (N_NODES + 1023) / 1024;   // 98

    k_prep<<<(N_NODES + 255) / 256, 256>>>(W2);
    k_deg<<<EB, 256>>>(dst);
    k_pretrans<<<(N_NODES + 127) / 128, 256>>>(h, W1);
    k_scan1<<<NB1, 1024>>>();
    k_scan2<<<1, 128>>>(NB1);
    k_scan3<<<(N_NODES + 255) / 256, 256>>>();
    k_scatter<<<EB, 256>>>(src, dst, eig);
    k_gather<<<N_NODES / 8, 256>>>();

    k_post<<<(N_NODES + 127) / 128, 256>>>(h, snorm, b1, b2);
    k_bn<<<1, 64>>>(gamma, beta);
    k_final<<<(N_NODES * D / 4 + 255) / 256, 256>>>(h, out);
}

// round 16
// speedup vs baseline: 2.4960x; 1.2877x over previous
#include <cuda_runtime.h>
#include <math.h>

#define N_NODES 100000
#define N_EDGES 1250000
#define D 64
#define EPSF 1e-8f
#define NEG_INF __int_as_float(0xff800000)

// ---------------- scratch (static device memory; no allocation) ----------------
__device__ float g_A[N_NODES * D];      // h @ W1[:, :64].T
__device__ float g_B[N_NODES * D];      // h @ W1[:, 64:].T
__device__ float g_mean[N_NODES * D];   // FINALIZED mean aggregate
__device__ float g_max[N_NODES * D];    // FINALIZED max aggregate
__device__ float g_dir[N_NODES * D];    // FINALIZED dir aggregate
__device__ float g_h2[N_NODES * D];     // posttrans output (pre-BN)
__device__ float g_stats[2 * D];        // per-feature sum, sumsq of h2
__device__ float g_scale[D];            // BN scale
__device__ float g_shift[D];            // BN shift
__device__ float g_W2T[256 * D];        // W2 transposed: [k][o]
// CSR machinery
__device__ int g_degi[N_NODES];         // int degree
__device__ int g_start[N_NODES];        // CSR row start (exclusive scan)
__device__ int g_cursor[N_NODES];       // scatter cursors
__device__ int2 g_epack[N_EDGES];       // (src, eig bits) grouped by dst
__device__ int g_bsum[128];             // scan block sums

// ---------------- K0: prep (zero degi/stats + transpose W2) ----------------
__global__ __launch_bounds__(256) void k_prep(const float* __restrict__ W2) {
    int i = blockIdx.x * 256 + threadIdx.x;
    if (i < N_NODES) g_degi[i] = 0;
    if (i < 2 * D) g_stats[i] = 0.0f;
    if (i < D * 256) {            // i = o*256 + k
        int o = i >> 8, k = i & 255;
        g_W2T[k * D + o] = W2[i];
    }
}

// ---------------- K1: node pretrans  A,B = h @ [W1a|W1b].T ----------------
// 256 threads, 128 nodes/block. Thread tile: 8 nodes x 8 outputs (out dim 128).
// (Round-10 proven: 63.9us, issue=53.8%)
#define WT_S 132   // sWt row stride (float4-aligned; 4-way STS conflict at worst)
#define HT_S 129   // sHt row stride (conflict-free STS and LDS)
__global__ __launch_bounds__(256) void k_pretrans(const float* __restrict__ h,
                                                  const float* __restrict__ W1) {
    __shared__ __align__(16) float sWt[64 * WT_S]; // [k][o] o<64 -> A, o>=64 -> B
    __shared__ float sHt[64 * HT_S];               // [k][node_local]
    int t = threadIdx.x;
    int base = blockIdx.x * 128;

    for (int idx = t; idx < 64 * 128; idx += 256) {
        int o = idx >> 7, kk = idx & 127;
        float v = W1[idx];                 // W1 row-major [o][kk]
        if (kk < D) sWt[kk * WT_S + o] = v;
        else        sWt[(kk - D) * WT_S + o + D] = v;
    }
    for (int idx = t; idx < 128 * 64; idx += 256) {
        int nl = idx >> 6, k = idx & 63;
        int n = base + nl;
        sHt[k * HT_S + nl] = (n < N_NODES) ? h[n * D + k] : 0.0f;
    }
    __syncthreads();

    int tx = t & 15, ty = t >> 4;   // tx: 8 outputs each (128 total); ty: 8 nodes each
    float acc[8][8];
#pragma unroll
    for (int i = 0; i < 8; i++)
#pragma unroll
        for (int j = 0; j < 8; j++) acc[i][j] = 0.0f;

#pragma unroll 2
    for (int k = 0; k < 64; k++) {
        float4 b0 = *reinterpret_cast<float4*>(&sWt[k * WT_S + tx * 8]);
        float4 b1v = *reinterpret_cast<float4*>(&sWt[k * WT_S + tx * 8 + 4]);
#pragma unroll
        for (int i = 0; i < 8; i++) {
            float a = sHt[k * HT_S + ty * 8 + i];
            acc[i][0] += a * b0.x;  acc[i][1] += a * b0.y;
            acc[i][2] += a * b0.z;  acc[i][3] += a * b0.w;
            acc[i][4] += a * b1v.x; acc[i][5] += a * b1v.y;
            acc[i][6] += a * b1v.z; acc[i][7] += a * b1v.w;
        }
    }

#pragma unroll
    for (int i = 0; i < 8; i++) {
        int n = base + ty * 8 + i;
        if (n >= N_NODES) continue;
        float4 v0 = make_float4(acc[i][0], acc[i][1], acc[i][2], acc[i][3]);
        float4 v1 = make_float4(acc[i][4], acc[i][5], acc[i][6], acc[i][7]);
        if (tx < 8) {
            *reinterpret_cast<float4*>(&g_A[n * D + tx * 8])     = v0;
            *reinterpret_cast<float4*>(&g_A[n * D + tx * 8 + 4]) = v1;
        } else {
            int o = tx * 8 - D;
            *reinterpret_cast<float4*>(&g_B[n * D + o])     = v0;
            *reinterpret_cast<float4*>(&g_B[n * D + o + 4]) = v1;
        }
    }
}

// ---------------- CSR build ----------------
__global__ __launch_bounds__(256) void k_deg(const int* __restrict__ dst) {
    int e = blockIdx.x * 256 + threadIdx.x;
    if (e < N_EDGES) atomicAdd(&g_degi[__ldg(&dst[e])], 1);
}

__global__ __launch_bounds__(1024) void k_scan1() {
    __shared__ int wsum[32];
    int t = threadIdx.x;
    int lane = t & 31, wid = t >> 5;
    int n = blockIdx.x * 1024 + t;
    int v = (n < N_NODES) ? g_degi[n] : 0;
    int inc = v;
#pragma unroll
    for (int off = 1; off < 32; off <<= 1) {
        int y = __shfl_up_sync(0xffffffffu, inc, off);
        if (lane >= off) inc += y;
    }
    if (lane == 31) wsum[wid] = inc;
    __syncthreads();
    if (wid == 0) {
        int s = wsum[lane];
        int inc2 = s;
#pragma unroll
        for (int off = 1; off < 32; off <<= 1) {
            int y = __shfl_up_sync(0xffffffffu, inc2, off);
            if (lane >= off) inc2 += y;
        }
        wsum[lane] = inc2 - s;            // exclusive warp offset
        if (lane == 31) g_bsum[blockIdx.x] = inc2;   // block total
    }
    __syncthreads();
    if (n < N_NODES) g_start[n] = inc - v + wsum[wid];
}

__global__ __launch_bounds__(128) void k_scan2(int nblk) {
    __shared__ int s[128];
    int t = threadIdx.x;
    int v = (t < nblk) ? g_bsum[t] : 0;
    s[t] = v;
    __syncthreads();
#pragma unroll
    for (int off = 1; off < 128; off <<= 1) {
        int x = (t >= off) ? s[t - off] : 0;
        __syncthreads();
        s[t] += x;
        __syncthreads();
    }
    if (t < nblk) g_bsum[t] = s[t] - v;   // exclusive
}

__global__ __launch_bounds__(256) void k_scan3() {
    int n = blockIdx.x * 256 + threadIdx.x;
    if (n < N_NODES) {
        int st = g_start[n] + g_bsum[n >> 10];
        g_start[n] = st;
        g_cursor[n] = st;
    }
}

__global__ __launch_bounds__(256) void k_scatter(const int* __restrict__ src,
                                                 const int* __restrict__ dst,
                                                 const float* __restrict__ eig) {
    int e = blockIdx.x * 256 + threadIdx.x;
    if (e < N_EDGES) {
        int d = __ldg(&dst[e]);
        int pos = atomicAdd(&g_cursor[d], 1);
        g_epack[pos] = make_int2(__ldg(&src[e]), __float_as_int(__ldg(&eig[e])));
    }
}

// ---------------- K2: CSR gather + aggregate FINALIZATION ----------------
// One warp per node; two 16-lane groups over alternating edges; final lanes
// load h/B/b1 rows and write finalized mean/max/dir (moves work out of k_post).
__global__ __launch_bounds__(256) void k_gather(const float* __restrict__ h,
                                                const float* __restrict__ b1) {
    int t = threadIdx.x;
    int n = blockIdx.x * 8 + (t >> 5);     // grid*8 == N_NODES exactly
    int lane = t & 31;
    int grp = lane >> 4;                   // 0/1
    int c = lane & 15;                     // feature quad

    int st = g_start[n];
    int deg = g_degi[n];
    int en = st + deg;

    float4 sum = make_float4(0.f, 0.f, 0.f, 0.f);
    float4 sw  = make_float4(0.f, 0.f, 0.f, 0.f);
    float4 mx  = make_float4(NEG_INF, NEG_INF, NEG_INF, NEG_INF);
    float ab = 0.f, sE = 0.f;

    int i = st + grp;
    for (; i + 2 < en; i += 4) {           // 2 edges in flight per group
        int2 pa = __ldg(&g_epack[i]);
        int2 pb = __ldg(&g_epack[i + 2]);
        float4 aa = *reinterpret_cast<const float4*>(&g_A[pa.x * D + c * 4]);
        float4 abv = *reinterpret_cast<const float4*>(&g_A[pb.x * D + c * 4]);
        float wa = __int_as_float(pa.y), wb = __int_as_float(pb.y);
        sum.x += aa.x + abv.x; sum.y += aa.y + abv.y;
        sum.z += aa.z + abv.z; sum.w += aa.w + abv.w;
        mx.x = fmaxf(mx.x, fmaxf(aa.x, abv.x)); mx.y = fmaxf(mx.y, fmaxf(aa.y, abv.y));
        mx.z = fmaxf(mx.z, fmaxf(aa.z, abv.z)); mx.w = fmaxf(mx.w, fmaxf(aa.w, abv.w));
        sw.x += wa * aa.x + wb * abv.x; sw.y += wa * aa.y + wb * abv.y;
        sw.z += wa * aa.z + wb * abv.z; sw.w += wa * aa.w + wb * abv.w;
        ab += fabsf(wa) + fabsf(wb); sE += wa + wb;
    }
    if (i < en) {
        int2 p = __ldg(&g_epack[i]);
        float w = __int_as_float(p.y);
        float4 a = *reinterpret_cast<const float4*>(&g_A[p.x * D + c * 4]);
        sum.x += a.x; sum.y += a.y; sum.z += a.z; sum.w += a.w;
        mx.x = fmaxf(mx.x, a.x); mx.y = fmaxf(mx.y, a.y);
        mx.z = fmaxf(mx.z, a.z); mx.w = fmaxf(mx.w, a.w);
        sw.x += w * a.x; sw.y += w * a.y; sw.z += w * a.z; sw.w += w * a.w;
        ab += fabsf(w); sE += w;
    }

    sum.x += __shfl_down_sync(0xffffffffu, sum.x, 16);
    sum.y += __shfl_down_sync(0xffffffffu, sum.y, 16);
    sum.z += __shfl_down_sync(0xffffffffu, sum.z, 16);
    sum.w += __shfl_down_sync(0xffffffffu, sum.w, 16);
    mx.x = fmaxf(mx.x, __shfl_down_sync(0xffffffffu, mx.x, 16));
    mx.y = fmaxf(mx.y, __shfl_down_sync(0xffffffffu, mx.y, 16));
    mx.z = fmaxf(mx.z, __shfl_down_sync(0xffffffffu, mx.z, 16));
    mx.w = fmaxf(mx.w, __shfl_down_sync(0xffffffffu, mx.w, 16));
    sw.x += __shfl_down_sync(0xffffffffu, sw.x, 16);
    sw.y += __shfl_down_sync(0xffffffffu, sw.y, 16);
    sw.z += __shfl_down_sync(0xffffffffu, sw.z, 16);
    sw.w += __shfl_down_sync(0xffffffffu, sw.w, 16);
    ab += __shfl_down_sync(0xffffffffu, ab, 16);
    sE += __shfl_down_sync(0xffffffffu, sE, 16);

    if (grp == 0) {
        int o = n * D + c * 4;
        // finalize using per-node scalars (registers) + h/B/b1 rows
        float4 Bv  = *reinterpret_cast<const float4*>(&g_B[o]);
        float4 hv  = *reinterpret_cast<const float4*>(&h[o]);
        float4 b1v = *reinterpret_cast<const float4*>(&b1[c * 4]);
        float degf = (float)deg;
        float invd = 1.0f / fmaxf(degf, 1.0f);
        float inva = 1.0f / (ab + EPSF);
        float swn = sE * inva;              // seg(w)
        float4 Bb = make_float4(Bv.x + b1v.x, Bv.y + b1v.y, Bv.z + b1v.z, Bv.w + b1v.w);
        float4 mean, mxo, dir;
        mean.x = (sum.x + degf * Bb.x) * invd;
        mean.y = (sum.y + degf * Bb.y) * invd;
        mean.z = (sum.z + degf * Bb.z) * invd;
        mean.w = (sum.w + degf * Bb.w) * invd;
        bool has = deg > 0;
        mxo.x = has ? (mx.x + Bb.x) : 0.0f;
        mxo.y = has ? (mx.y + Bb.y) : 0.0f;
        mxo.z = has ? (mx.z + Bb.z) : 0.0f;
        mxo.w = has ? (mx.w + Bb.w) : 0.0f;
        dir.x = fabsf((sw.x + sE * Bb.x) * inva - swn * hv.x);
        dir.y = fabsf((sw.y + sE * Bb.y) * inva - swn * hv.y);
        dir.z = fabsf((sw.z + sE * Bb.z) * inva - swn * hv.z);
        dir.w = fabsf((sw.w + sE * Bb.w) * inva - swn * hv.w);
        *reinterpret_cast<float4*>(&g_mean[o]) = mean;
        *reinterpret_cast<float4*>(&g_max[o])  = mxo;
        *reinterpret_cast<float4*>(&g_dir[o])  = dir;
    }
}

// ---------------- K4: node posttrans GEMM + BN partial stats ----------------
// 256 threads, 128 nodes/block (Round-9 proven GEMM config).
// hc-build is now a pure streaming copy of 4 precomputed arrays.
#define HC_S 66
__global__ __launch_bounds__(256) void k_post(const float* __restrict__ h,
                                              const float* __restrict__ snorm,
                                              const float* __restrict__ b2) {
    __shared__ float sHC[128 * HC_S];            // [node][k] one chunk
    __shared__ __align__(16) float sW2[64 * 64]; // [k][o] one chunk of W2T
    __shared__ float sStats[2 * D];

    int t = threadIdx.x;
    int base = blockIdx.x * 128;

    if (t < 128) sStats[t] = 0.0f;

    int f = t & 63;
    int quarter = t >> 6;          // 0..3

    int tx = t & 7, ty = t >> 3;   // tx: 8 outputs each; ty: 0..31, 4 nodes each
    float acc[4][8];
#pragma unroll
    for (int i = 0; i < 4; i++)
#pragma unroll
        for (int j = 0; j < 8; j++) acc[i][j] = 0.0f;

#pragma unroll
    for (int cch = 0; cch < 4; cch++) {
        const float* srcArr = (cch == 0) ? h : (cch == 1) ? g_mean
                              : (cch == 2) ? g_max : g_dir;
        __syncthreads();
#pragma unroll
        for (int i = t * 4; i < 4096; i += 1024)
            *reinterpret_cast<float4*>(&sW2[i]) =
                *reinterpret_cast<const float4*>(&g_W2T[cch * 4096 + i]);
        for (int r = 0; r < 32; r++) {
            int nl = quarter + r * 4;
            int n = base + nl;
            float v = (n < N_NODES) ? __ldg(&srcArr[n * D + f]) : 0.0f;
            sHC[nl * HC_S + f] = v;
        }
        __syncthreads();
#pragma unroll 4
        for (int k = 0; k < 64; k++) {
            float4 b0 = *reinterpret_cast<float4*>(&sW2[k * 64 + tx * 8]);
            float4 b1v = *reinterpret_cast<float4*>(&sW2[k * 64 + tx * 8 + 4]);
#pragma unroll
            for (int i = 0; i < 4; i++) {
                float a = sHC[(ty * 4 + i) * HC_S + k];
                acc[i][0] += a * b0.x;  acc[i][1] += a * b0.y;
                acc[i][2] += a * b0.z;  acc[i][3] += a * b0.w;
                acc[i][4] += a * b1v.x; acc[i][5] += a * b1v.y;
                acc[i][6] += a * b1v.z; acc[i][7] += a * b1v.w;
            }
        }
    }

    float4 bA = *reinterpret_cast<const float4*>(&b2[tx * 8]);
    float4 bB = *reinterpret_cast<const float4*>(&b2[tx * 8 + 4]);
    float s0 = 0, s1 = 0, s2 = 0, s3 = 0, s4 = 0, s5 = 0, s6 = 0, s7 = 0;
    float q0 = 0, q1 = 0, q2 = 0, q3 = 0, q4 = 0, q5 = 0, q6 = 0, q7 = 0;
#pragma unroll
    for (int i = 0; i < 4; i++) {
        int n = base + ty * 4 + i;
        if (n >= N_NODES) continue;
        float sn = __ldg(&snorm[n]);
        float4 oA, oB;
        oA.x = (acc[i][0] + bA.x) * sn; oA.y = (acc[i][1] + bA.y) * sn;
        oA.z = (acc[i][2] + bA.z) * sn; oA.w = (acc[i][3] + bA.w) * sn;
        oB.x = (acc[i][4] + bB.x) * sn; oB.y = (acc[i][5] + bB.y) * sn;
        oB.z = (acc[i][6] + bB.z) * sn; oB.w = (acc[i][7] + bB.w) * sn;
        *reinterpret_cast<float4*>(&g_h2[n * D + tx * 8])     = oA;
        *reinterpret_cast<float4*>(&g_h2[n * D + tx * 8 + 4]) = oB;
        s0 += oA.x; s1 += oA.y; s2 += oA.z; s3 += oA.w;
        s4 += oB.x; s5 += oB.y; s6 += oB.z; s7 += oB.w;
        q0 += oA.x * oA.x; q1 += oA.y * oA.y; q2 += oA.z * oA.z; q3 += oA.w * oA.w;
        q4 += oB.x * oB.x; q5 += oB.y * oB.y; q6 += oB.z * oB.z; q7 += oB.w * oB.w;
    }
    int ob = tx * 8;
    atomicAdd(&sStats[ob + 0], s0); atomicAdd(&sStats[ob + 1], s1);
    atomicAdd(&sStats[ob + 2], s2); atomicAdd(&sStats[ob + 3], s3);
    atomicAdd(&sStats[ob + 4], s4); atomicAdd(&sStats[ob + 5], s5);
    atomicAdd(&sStats[ob + 6], s6); atomicAdd(&sStats[ob + 7], s7);
    atomicAdd(&sStats[D + ob + 0], q0); atomicAdd(&sStats[D + ob + 1], q1);
    atomicAdd(&sStats[D + ob + 2], q2); atomicAdd(&sStats[D + ob + 3], q3);
    atomicAdd(&sStats[D + ob + 4], q4); atomicAdd(&sStats[D + ob + 5], q5);
    atomicAdd(&sStats[D + ob + 6], q6); atomicAdd(&sStats[D + ob + 7], q7);
    __syncthreads();
    if (t < 2 * D) atomicAdd(&g_stats[t], sStats[t]);
}

// ---------------- K5: BN scale/shift ----------------
__global__ void k_bn(const float* __restrict__ gamma, const float* __restrict__ beta) {
    int f = threadIdx.x;
    if (f < D) {
        const float inv = 1.0f / (float)N_NODES;
        float mu = g_stats[f] * inv;
        float var = g_stats[D + f] * inv - mu * mu;
        float sc = gamma[f] * rsqrtf(var + 1e-5f);
        g_scale[f] = sc;
        g_shift[f] = beta[f] - mu * sc;
    }
}

// ---------------- K6: final elementwise ----------------
__global__ __launch_bounds__(256) void k_final(const float* __restrict__ h,
                                               float* __restrict__ out) {
    int i = blockIdx.x * 256 + threadIdx.x;
    const int NV = (N_NODES * D) / 4;
    if (i >= NV) return;
    int f4 = (i & 15) * 4;
    float4 v = reinterpret_cast<const float4*>(g_h2)[i];
    float4 hv = reinterpret_cast<const float4*>(h)[i];
    float4 sc = *reinterpret_cast<const float4*>(&g_scale[f4]);
    float4 sh = *reinterpret_cast<const float4*>(&g_shift[f4]);
    float4 o;
    o.x = hv.x + fmaxf(v.x * sc.x + sh.x, 0.0f);
    o.y = hv.y + fmaxf(v.y * sc.y + sh.y, 0.0f);
    o.z = hv.z + fmaxf(v.z * sc.z + sh.z, 0.0f);
    o.w = hv.w + fmaxf(v.w * sc.w + sh.w, 0.0f);
    reinterpret_cast<float4*>(out)[i] = o;
}

// ---------------- launch ----------------
extern "C" void kernel_launch(void* const* d_in, const int* in_sizes, int n_in,
                              void* d_out, int out_size) {
    const float* h     = (const float*)d_in[0];
    const float* eig   = (const float*)d_in[1];
    const float* snorm = (const float*)d_in[2];
    const int*   src   = (const int*)d_in[3];
    const int*   dst   = (const int*)d_in[4];
    const float* W1    = (const float*)d_in[5];
    const float* b1    = (const float*)d_in[6];
    const float* W2    = (const float*)d_in[7];
    const float* b2    = (const float*)d_in[8];
    const float* gamma = (const float*)d_in[9];
    const float* beta  = (const float*)d_in[10];
    float* out = (float*)d_out;

    const int EB = (N_EDGES + 255) / 256;
    const int NB1 = (N_NODES + 1023) / 1024;   // 98

    k_prep<<<(N_NODES + 255) / 256, 256>>>(W2);
    k_deg<<<EB, 256>>>(dst);
    k_pretrans<<<(N_NODES + 127) / 128, 256>>>(h, W1);
    k_scan1<<<NB1, 1024>>>();
    k_scan2<<<1, 128>>>(NB1);
    k_scan3<<<(N_NODES + 255) / 256, 256>>>();
    k_scatter<<<EB, 256>>>(src, dst, eig);
    k_gather<<<N_NODES / 8, 256>>>(h, b1);

    k_post<<<(N_NODES + 127) / 128, 256>>>(h, snorm, b2);
    k_bn<<<1, 64>>>(gamma, beta);
    k_final<<<(N_NODES * D / 4 + 255) / 256, 256>>>(h, out);
}